// round 14
// baseline (speedup 1.0000x reference)
#include <cuda_runtime.h>

#define NN 100000
#define EE 1600000
#define NBLK1 391             // ceil(NN/256)
#define AE_BLOCKS (EE / 64)   // 25000 (64 edges per ae block)
#define N0_BLOCKS (NN / 16)   // 6250

typedef unsigned long long u64;

// ---------------- scratch (device globals; no allocation allowed) ----------
__device__ __align__(16) float g_ae1[EE * 4];    // CSR-SLOT-ordered layer-1 logits (25.6MB)
__device__ __align__(16) float g_ae2[EE * 4];    // CSR-SLOT-ordered layer-2 logits (25.6MB)
__device__ __align__(16) float g_xp[NN * 64];    // layer-1 projected feats
__device__ __align__(16) float g_xp2[NN * 64];   // layer-2 projected feats
__device__ int   g_el[EE];                        // CSR: src node per slot (6.4MB)
__device__ int   g_pos[EE];                       // edge id -> CSR slot (6.4MB)
__device__ float g_asrc[NN * 4],  g_adst[NN * 4];    // layer-1 att dots
__device__ float g_asrc2[NN * 4], g_adst2[NN * 4];   // layer-2 att dots
__device__ int   g_cnt[NN];
__device__ int   g_off[NN];
__device__ int   g_cur[NN];      // fill cursor; after fill = segment end
__device__ int   g_total;        // bump allocator
__device__ float g_P[512];       // folded [64 j][8 h]
__device__ float g_W1t[64 * 128];   // transposed weights [c][k]
__device__ float g_W2t[64 * 64];
__device__ float g_Wot[64 * 64];

// ---------------------------------------------------------------------------
__device__ __forceinline__ u64 ffma2(u64 a, u64 b, u64 c) {
    u64 d;
    asm("fma.rn.f32x2 %0, %1, %2, %3;" : "=l"(d) : "l"(a), "l"(b), "l"(c));
    return d;
}
__device__ __forceinline__ float hsum2(u64 p) {
    return __uint_as_float((unsigned)p) + __uint_as_float((unsigned)(p >> 32));
}

// edge_index dtype hedge (int64 vs int32): int64 little-endian has zero odd words.
__device__ __forceinline__ bool ei_is64(const int* __restrict__ ei) {
    return (ei[1] | ei[3] | ei[5] | ei[7]) == 0;
}
__device__ __forceinline__ int ei_load(const int* __restrict__ ei, long long pos, bool is64) {
    return is64 ? ei[pos * 2] : ei[pos];
}

// ---------------------------------------------------------------------------
// setup: blocks 0..390 zero g_cnt (+g_total); block 391 folds P; blocks
// 392..423 transpose the three weight matrices.
// ---------------------------------------------------------------------------
__global__ void __launch_bounds__(256) setup_kernel(const float* __restrict__ We1,
                                                    const float* __restrict__ We2,
                                                    const float* __restrict__ ate1,
                                                    const float* __restrict__ ate2,
                                                    const float* __restrict__ W1,
                                                    const float* __restrict__ W2,
                                                    const float* __restrict__ Wo) {
    int b = blockIdx.x, t = threadIdx.x;
    if (b < NBLK1) {
        int i = b * 256 + t;
        if (i < NN) g_cnt[i] = 0;
        if (b == 0 && t == 0) g_total = 0;
    } else if (b == NBLK1) {
        __shared__ float A2p[64 * 4];
        int j = t;
        if (j < 64) {
#pragma unroll
            for (int h = 0; h < 4; h++) {
                float s = 0.f;
#pragma unroll
                for (int c = 0; c < 16; c++) s += We2[j * 64 + h * 16 + c] * ate2[h * 16 + c];
                A2p[j * 4 + h] = s;
            }
        }
        __syncthreads();
        if (j < 64) {
#pragma unroll
            for (int h = 0; h < 4; h++) {
                float s = 0.f;
#pragma unroll
                for (int c = 0; c < 16; c++) s += We1[j * 64 + h * 16 + c] * ate1[h * 16 + c];
                g_P[j * 8 + h] = s;
            }
#pragma unroll
            for (int h = 0; h < 4; h++) {
                float s = 0.f;
                for (int k = 0; k < 64; k++) s += We1[j * 64 + k] * A2p[k * 4 + h];
                g_P[j * 8 + 4 + h] = s;
            }
        }
    } else {
        int i = (b - NBLK1 - 1) * 256 + t;   // 0..8191
        int k = i >> 6, c = i & 63;
        g_W1t[c * 128 + k] = W1[i];
        if (i < 4096) {
            g_W2t[c * 64 + k] = W2[i];
            g_Wot[c * 64 + k] = Wo[i];
        }
    }
}

// ---------------------------------------------------------------------------
// CSR build helpers: histogram, warp-aggregated bump alloc, fill
// (alloc order arbitrary-but-consistent; per-node sums unaffected)
// ---------------------------------------------------------------------------
__global__ void hist_kernel(const int* __restrict__ ei) {
    int e = blockIdx.x * 256 + threadIdx.x;
    bool is64 = ei_is64(ei);
    int d = ei_load(ei, (long long)EE + e, is64);
    atomicAdd(&g_cnt[d], 1);
}
__global__ void __launch_bounds__(256) alloc_kernel() {
    int i = blockIdx.x * 256 + threadIdx.x;
    int lane = threadIdx.x & 31;
    int c = (i < NN) ? g_cnt[i] : 0;
    int incl = c;
#pragma unroll
    for (int o = 1; o < 32; o <<= 1) {
        int v = __shfl_up_sync(0xffffffffu, incl, o);
        if (lane >= o) incl += v;
    }
    int wsum = __shfl_sync(0xffffffffu, incl, 31);
    int base = 0;
    if (lane == 31) base = atomicAdd(&g_total, wsum);
    base = __shfl_sync(0xffffffffu, base, 31);
    if (i < NN) {
        int off = base + incl - c;
        g_off[i] = off;
        g_cur[i] = off;
    }
}
__global__ void fill_kernel(const int* __restrict__ ei) {
    int e = blockIdx.x * 256 + threadIdx.x;
    bool is64 = ei_is64(ei);
    int s = ei_load(ei, e, is64);
    int d = ei_load(ei, (long long)EE + e, is64);
    int pos = atomicAdd(&g_cur[d], 1);
    g_el[pos] = s;
    g_pos[e] = pos;
}

// ---------------------------------------------------------------------------
// FUSED kernel: blocks [0, AE_BLOCKS) = ae body (64 edges/block, 2-edge
// P-register reuse; logits written at the edge's CSR SLOT so gathers read
// sequentially); rest = layer-1 node GEMM (proven).
// ---------------------------------------------------------------------------
__global__ void __launch_bounds__(256) fused_ae_node0_kernel(
        const float* __restrict__ edge_attr,
        const float* __restrict__ xin,
        const float* __restrict__ attS,
        const float* __restrict__ attD) {
    __shared__ __align__(16) char sbuf[26368];
    int t = threadIdx.x;

    if (blockIdx.x < AE_BLOCKS) {
        // ---- ae body: slot(e) gets mean(edge_attr[e]) @ P halves ----------
        float* sEas = (float*)sbuf;            // 64 x 68 floats (17408B)
        float* sPt = (float*)(sbuf + 17408);   // 8 x 68 (transposed P, 2176B)
        int* sPos = (int*)(sbuf + 19584);      // 64 slots (256B)
        const float4* __restrict__ ea4 = (const float4*)edge_attr;
        long long e0 = (long long)blockIdx.x * 64;

#pragma unroll
        for (int i = 0; i < 2; i++) {
            int idx = t + i * 256;
            sPt[(idx & 7) * 68 + (idx >> 3)] = g_P[idx];
        }
        if (t < 64) sPos[t] = g_pos[e0 + t];
#pragma unroll
        for (int i = 0; i < 4; i++) {
            int idx = t + i * 256;           // 0..1023
            int e = idx >> 4, j4 = idx & 15;
            long long base = (e0 + e) * 48;
            float4 a = ea4[base + j4];
            float4 b = ea4[base + 16 + j4];
            float4 c = ea4[base + 32 + j4];
            float4 m = make_float4((a.x + b.x + c.x) * (1.f / 3.f),
                                   (a.y + b.y + c.y) * (1.f / 3.f),
                                   (a.z + b.z + c.z) * (1.f / 3.f),
                                   (a.w + b.w + c.w) * (1.f / 3.f));
            *(float4*)&sEas[e * 68 + j4 * 4] = m;
        }
        __syncthreads();

        // thread -> (edge pair g = t>>3, head h = t&7); pr reused for 2 edges
        int g = t >> 3, h = t & 7;
        const float* erA = &sEas[(g * 2 + 0) * 68];
        const float* erB = &sEas[(g * 2 + 1) * 68];
        const float* pr = &sPt[h * 68];
        float accA = 0.f, accB = 0.f;
#pragma unroll
        for (int j4 = 0; j4 < 16; j4++) {
            float4 p = *(const float4*)&pr[j4 * 4];
            float4 uA = *(const float4*)&erA[j4 * 4];
            float4 uB = *(const float4*)&erB[j4 * 4];
            accA += uA.x * p.x + uA.y * p.y + uA.z * p.z + uA.w * p.w;
            accB += uB.x * p.x + uB.y * p.y + uB.z * p.z + uB.w * p.w;
        }
        size_t pA = (size_t)sPos[g * 2], pB = (size_t)sPos[g * 2 + 1];
        if (h < 4) {
            g_ae1[pA * 4 + h] = accA;
            g_ae1[pB * 4 + h] = accB;
        } else {
            g_ae2[pA * 4 + (h - 4)] = accA;
            g_ae2[pB * 4 + (h - 4)] = accB;
        }
    } else {
        // ---------------- layer-1 node GEMM (IN=128), K staged in 2 halves --
        const int INp = 132;
        float* Wts = (float*)sbuf;                     // 64 x 68 (one K half)
        float* xs = (float*)(sbuf + 17408);            // 16 x 132
        float* aSs = (float*)(sbuf + 25856);
        float* aDs = (float*)(sbuf + 26112);
        int nb0 = (blockIdx.x - AE_BLOCKS) * 16;

        for (int i = t; i < 16 * 128; i += 256)
            xs[(i >> 7) * INp + (i & 127)] = xin[(size_t)nb0 * 128 + i];
        if (t < 64) { aSs[t] = attS[t]; aDs[t] = attD[t]; }

        int c = t & 63, q = t >> 6;
        u64 p0 = 0ull, p1 = 0ull, p2 = 0ull, p3 = 0ull;
#pragma unroll
        for (int half = 0; half < 2; half++) {
            __syncthreads();
            for (int i = t; i < 4096; i += 256) {
                int cc = i >> 6, kk = i & 63;
                Wts[cc * 68 + kk] = g_W1t[cc * 128 + half * 64 + kk];
            }
            __syncthreads();
            const float* wr = &Wts[c * 68];
            const float* x0 = &xs[(q * 4 + 0) * INp + half * 64];
            const float* x1 = &xs[(q * 4 + 1) * INp + half * 64];
            const float* x2 = &xs[(q * 4 + 2) * INp + half * 64];
            const float* x3 = &xs[(q * 4 + 3) * INp + half * 64];
#pragma unroll
            for (int k = 0; k < 64; k += 4) {
                ulonglong2 w  = *(const ulonglong2*)&wr[k];
                ulonglong2 u0 = *(const ulonglong2*)&x0[k];
                ulonglong2 u1 = *(const ulonglong2*)&x1[k];
                ulonglong2 u2 = *(const ulonglong2*)&x2[k];
                ulonglong2 u3 = *(const ulonglong2*)&x3[k];
                p0 = ffma2(w.x, u0.x, p0); p0 = ffma2(w.y, u0.y, p0);
                p1 = ffma2(w.x, u1.x, p1); p1 = ffma2(w.y, u1.y, p1);
                p2 = ffma2(w.x, u2.x, p2); p2 = ffma2(w.y, u2.y, p2);
                p3 = ffma2(w.x, u3.x, p3); p3 = ffma2(w.y, u3.y, p3);
            }
        }
        float av[4] = {hsum2(p0), hsum2(p1), hsum2(p2), hsum2(p3)};
        float aS = aSs[c], aD = aDs[c];
        int lane = t & 31, head = c >> 4;
        int nb = nb0 + q * 4;
#pragma unroll
        for (int j = 0; j < 4; j++) {
            g_xp[(size_t)(nb + j) * 64 + c] = av[j];
            float r1 = av[j] * aS;
            float r2 = av[j] * aD;
#pragma unroll
            for (int o = 8; o; o >>= 1) {
                r1 += __shfl_xor_sync(0xffffffffu, r1, o);
                r2 += __shfl_xor_sync(0xffffffffu, r2, o);
            }
            if ((lane & 15) == 0) {
                g_asrc[(nb + j) * 4 + head] = r1;
                g_adst[(nb + j) * 4 + head] = r2;
            }
        }
    }
}

// ---------------------------------------------------------------------------
// FUSED gather + node GEMM (proven). Block = 16 nodes.
// Gather: 16 groups of 16 lanes; lane owns a float4 of channels (head gl>>2).
// ae reads are SEQUENTIAL (CSR-slot order); edge list is src-only int.
// GEMM: register-blocked f32x2 on the smem tile.
// ---------------------------------------------------------------------------
template <int LAYER>
__global__ void __launch_bounds__(256) gather_node_kernel(const float* __restrict__ attS,
                                                          const float* __restrict__ attD,
                                                          const float* __restrict__ bias,
                                                          float* __restrict__ outp) {
    const int INp = 68;
    __shared__ float Wts[64 * INp];
    __shared__ float xs[16 * INp];
    __shared__ float aSs[64], aDs[64];
    int t = threadIdx.x;
    const float* __restrict__ Wt = (LAYER == 1) ? g_W2t : g_Wot;
    for (int i = t; i < 64 * 64; i += 256) Wts[(i >> 6) * INp + (i & 63)] = Wt[i];
    if (LAYER == 1 && t < 64) { aSs[t] = attS[t]; aDs[t] = attD[t]; }

    // ---- gather phase ----
    int grp = t >> 4, gl = t & 15;
    int nb0 = blockIdx.x * 16;
    int n = nb0 + grp;
    int h = gl >> 2;
    const float* __restrict__ aSrc = (LAYER == 1) ? g_asrc : g_asrc2;
    const float* __restrict__ aDst = (LAYER == 1) ? g_adst : g_adst2;
    const float* __restrict__ aeL = (LAYER == 1) ? g_ae1 : g_ae2;
    const float4* __restrict__ xp4 =
        (const float4*)((LAYER == 1) ? g_xp : g_xp2);
    float aD = aDst[n * 4 + h];
    int p = g_off[n], pend = g_cur[n];
    float4 acc = make_float4(0.f, 0.f, 0.f, 0.f);
    float den = 0.f;
#pragma unroll 4
    for (; p < pend; p++) {
        int s = g_el[p];
        float a = aSrc[s * 4 + h] + aD + aeL[(size_t)p * 4 + h];
        a = a > 0.f ? a : 0.2f * a;
        float w = __expf(a);
        float4 v = xp4[s * 16 + gl];
        acc.x += w * v.x;
        acc.y += w * v.y;
        acc.z += w * v.z;
        acc.w += w * v.w;
        den += w;
    }
    float inv = 1.f / fmaxf(den, 1e-16f);
    *(float4*)&xs[grp * INp + gl * 4] =
        make_float4(fmaxf(acc.x * inv, 0.f), fmaxf(acc.y * inv, 0.f),
                    fmaxf(acc.z * inv, 0.f), fmaxf(acc.w * inv, 0.f));
    __syncthreads();

    // ---- GEMM phase ----
    int c = t & 63, q = t >> 6;
    const float* wr = &Wts[c * INp];
    const float* x0 = &xs[(q * 4 + 0) * INp];
    const float* x1 = &xs[(q * 4 + 1) * INp];
    const float* x2 = &xs[(q * 4 + 2) * INp];
    const float* x3 = &xs[(q * 4 + 3) * INp];
    u64 p0 = 0ull, p1 = 0ull, p2 = 0ull, p3 = 0ull;
#pragma unroll
    for (int k = 0; k < 64; k += 4) {
        ulonglong2 w  = *(const ulonglong2*)&wr[k];
        ulonglong2 u0 = *(const ulonglong2*)&x0[k];
        ulonglong2 u1 = *(const ulonglong2*)&x1[k];
        ulonglong2 u2 = *(const ulonglong2*)&x2[k];
        ulonglong2 u3 = *(const ulonglong2*)&x3[k];
        p0 = ffma2(w.x, u0.x, p0); p0 = ffma2(w.y, u0.y, p0);
        p1 = ffma2(w.x, u1.x, p1); p1 = ffma2(w.y, u1.y, p1);
        p2 = ffma2(w.x, u2.x, p2); p2 = ffma2(w.y, u2.y, p2);
        p3 = ffma2(w.x, u3.x, p3); p3 = ffma2(w.y, u3.y, p3);
    }
    float a0 = hsum2(p0), a1 = hsum2(p1), a2 = hsum2(p2), a3 = hsum2(p3);
    int nb = nb0 + q * 4;
    if (LAYER == 2) {
        float b = bias[c];
        outp[(size_t)(nb + 0) * 64 + c] = a0 + b;
        outp[(size_t)(nb + 1) * 64 + c] = a1 + b;
        outp[(size_t)(nb + 2) * 64 + c] = a2 + b;
        outp[(size_t)(nb + 3) * 64 + c] = a3 + b;
    } else {
        float aS = aSs[c], aDv = aDs[c];
        int lane = t & 31, head = c >> 4;
        float av[4] = {a0, a1, a2, a3};
#pragma unroll
        for (int j = 0; j < 4; j++) {
            g_xp2[(size_t)(nb + j) * 64 + c] = av[j];
            float r1 = av[j] * aS;
            float r2 = av[j] * aDv;
#pragma unroll
            for (int o = 8; o; o >>= 1) {
                r1 += __shfl_xor_sync(0xffffffffu, r1, o);
                r2 += __shfl_xor_sync(0xffffffffu, r2, o);
            }
            if ((lane & 15) == 0) {
                g_asrc2[(nb + j) * 4 + head] = r1;
                g_adst2[(nb + j) * 4 + head] = r2;
            }
        }
    }
}

// ---------------------------------------------------------------------------
extern "C" void kernel_launch(void* const* d_in, const int* in_sizes, int n_in,
                              void* d_out, int out_size) {
    const float* x = (const float*)d_in[0];
    const int* ei = (const int*)d_in[1];
    const float* edge_attr = (const float*)d_in[2];
    const float* W1 = (const float*)d_in[3];
    const float* We1 = (const float*)d_in[4];
    const float* as1 = (const float*)d_in[5];
    const float* ad1 = (const float*)d_in[6];
    const float* ae1 = (const float*)d_in[7];
    const float* W2 = (const float*)d_in[8];
    const float* We2 = (const float*)d_in[9];
    const float* as2 = (const float*)d_in[10];
    const float* ad2 = (const float*)d_in[11];
    const float* ae2 = (const float*)d_in[12];
    const float* Wout = (const float*)d_in[13];
    const float* bout = (const float*)d_in[14];
    float* out = (float*)d_out;

    // 1: zero cnt/total + P fold + weight transpose
    setup_kernel<<<NBLK1 + 1 + 32, 256>>>(We1, We2, ae1, ae2, W1, W2, Wout);
    // 2-4: CSR build (histogram -> bump alloc -> fill records slot per edge)
    hist_kernel<<<EE / 256, 256>>>(ei);
    alloc_kernel<<<NBLK1, 256>>>();
    fill_kernel<<<EE / 256, 256>>>(ei);
    // 5: big fused kernel (ae stream -> CSR slots + layer-1 node GEMM)
    fused_ae_node0_kernel<<<AE_BLOCKS + N0_BLOCKS, 256>>>(edge_attr, x, as1, ad1);
    // 6: gather layer 1 + layer-2 node GEMM (writes xp2/att2)
    gather_node_kernel<1><<<NN / 16, 256>>>(as2, ad2, nullptr, nullptr);
    // 7: gather layer 2 + output GEMM
    gather_node_kernel<2><<<NN / 16, 256>>>(nullptr, nullptr, bout, out);
}

// round 15
// speedup vs baseline: 1.0452x; 1.0452x over previous
#include <cuda_runtime.h>

#define NN 100000
#define EE 1600000
#define NBLK1 391             // ceil(NN/256)
#define AE_BLOCKS (EE / 64)   // 25000 (64 edges per ae block)
#define N0_BLOCKS (NN / 16)   // 6250
#define HIST_BLOCKS (EE / 256) // 6250

typedef unsigned long long u64;

// ---------------- scratch (device globals; no allocation allowed) ----------
__device__ __align__(16) float g_ae1[EE * 4];    // EDGE-ordered layer-1 logits (25.6MB)
__device__ __align__(16) float g_ae2[EE * 4];    // EDGE-ordered layer-2 logits (25.6MB)
__device__ __align__(16) float g_xp[NN * 64];    // layer-1 projected feats
__device__ __align__(16) float g_xp2[NN * 64];   // layer-2 projected feats
__device__ __align__(16) int2  g_el2[EE];        // CSR: (src, edge_id) per slot
__device__ float g_asrc[NN * 4],  g_adst[NN * 4];    // layer-1 att dots
__device__ float g_asrc2[NN * 4], g_adst2[NN * 4];   // layer-2 att dots
__device__ int   g_cnt[NN];
__device__ int   g_off[NN];
__device__ int   g_cur[NN];      // fill cursor; after fill = segment end
__device__ int   g_total;        // bump allocator
__device__ float g_P[512];       // folded [64 j][8 h]
__device__ float g_W1t[64 * 128];   // transposed weights [c][k]
__device__ float g_W2t[64 * 64];
__device__ float g_Wot[64 * 64];

// ---------------------------------------------------------------------------
__device__ __forceinline__ u64 ffma2(u64 a, u64 b, u64 c) {
    u64 d;
    asm("fma.rn.f32x2 %0, %1, %2, %3;" : "=l"(d) : "l"(a), "l"(b), "l"(c));
    return d;
}
__device__ __forceinline__ float hsum2(u64 p) {
    return __uint_as_float((unsigned)p) + __uint_as_float((unsigned)(p >> 32));
}

// edge_index dtype hedge (int64 vs int32): int64 little-endian has zero odd words.
__device__ __forceinline__ bool ei_is64(const int* __restrict__ ei) {
    return (ei[1] | ei[3] | ei[5] | ei[7]) == 0;
}
__device__ __forceinline__ int ei_load(const int* __restrict__ ei, long long pos, bool is64) {
    return is64 ? ei[pos * 2] : ei[pos];
}

// ---------------------------------------------------------------------------
// setup: blocks 0..390 zero g_cnt (+g_total); block 391 folds P; blocks
// 392..423 transpose the three weight matrices.
// ---------------------------------------------------------------------------
__global__ void __launch_bounds__(256) setup_kernel(const float* __restrict__ We1,
                                                    const float* __restrict__ We2,
                                                    const float* __restrict__ ate1,
                                                    const float* __restrict__ ate2,
                                                    const float* __restrict__ W1,
                                                    const float* __restrict__ W2,
                                                    const float* __restrict__ Wo) {
    int b = blockIdx.x, t = threadIdx.x;
    if (b < NBLK1) {
        int i = b * 256 + t;
        if (i < NN) g_cnt[i] = 0;
        if (b == 0 && t == 0) g_total = 0;
    } else if (b == NBLK1) {
        __shared__ float A2p[64 * 4];
        int j = t;
        if (j < 64) {
#pragma unroll
            for (int h = 0; h < 4; h++) {
                float s = 0.f;
#pragma unroll
                for (int c = 0; c < 16; c++) s += We2[j * 64 + h * 16 + c] * ate2[h * 16 + c];
                A2p[j * 4 + h] = s;
            }
        }
        __syncthreads();
        if (j < 64) {
#pragma unroll
            for (int h = 0; h < 4; h++) {
                float s = 0.f;
#pragma unroll
                for (int c = 0; c < 16; c++) s += We1[j * 64 + h * 16 + c] * ate1[h * 16 + c];
                g_P[j * 8 + h] = s;
            }
#pragma unroll
            for (int h = 0; h < 4; h++) {
                float s = 0.f;
                for (int k = 0; k < 64; k++) s += We1[j * 64 + k] * A2p[k * 4 + h];
                g_P[j * 8 + 4 + h] = s;
            }
        }
    } else {
        int i = (b - NBLK1 - 1) * 256 + t;   // 0..8191
        int k = i >> 6, c = i & 63;
        g_W1t[c * 128 + k] = W1[i];
        if (i < 4096) {
            g_W2t[c * 64 + k] = W2[i];
            g_Wot[c * 64 + k] = Wo[i];
        }
    }
}

// ---------------------------------------------------------------------------
// CSR build helpers: warp-aggregated bump alloc, fill
// (histogram lives inside the fused kernel; alloc order arbitrary-but-
//  consistent; per-node sums unaffected)
// ---------------------------------------------------------------------------
__global__ void __launch_bounds__(256) alloc_kernel() {
    int i = blockIdx.x * 256 + threadIdx.x;
    int lane = threadIdx.x & 31;
    int c = (i < NN) ? g_cnt[i] : 0;
    int incl = c;
#pragma unroll
    for (int o = 1; o < 32; o <<= 1) {
        int v = __shfl_up_sync(0xffffffffu, incl, o);
        if (lane >= o) incl += v;
    }
    int wsum = __shfl_sync(0xffffffffu, incl, 31);
    int base = 0;
    if (lane == 31) base = atomicAdd(&g_total, wsum);
    base = __shfl_sync(0xffffffffu, base, 31);
    if (i < NN) {
        int off = base + incl - c;
        g_off[i] = off;
        g_cur[i] = off;
    }
}
__global__ void fill_kernel(const int* __restrict__ ei) {
    int e = blockIdx.x * 256 + threadIdx.x;
    bool is64 = ei_is64(ei);
    int s = ei_load(ei, e, is64);
    int d = ei_load(ei, (long long)EE + e, is64);
    int pos = atomicAdd(&g_cur[d], 1);
    g_el2[pos] = make_int2(s, e);
}

// ---------------------------------------------------------------------------
// FUSED kernel, 3 sequential block ranges:
//  [0, AE_BLOCKS)            : ae body (64 edges/block, 2-edge P-register
//                              reuse; coalesced edge-ordered writes)
//  [AE, AE+N0)               : layer-1 node GEMM (IN=128, f32x2, proven)
//  [AE+N0, AE+N0+HIST)       : in-degree histogram (independent; absorbed by
//                              the DRAM-bound phase)
// ---------------------------------------------------------------------------
__global__ void __launch_bounds__(256) fused_ae_node0_kernel(
        const float* __restrict__ edge_attr,
        const float* __restrict__ xin,
        const float* __restrict__ attS,
        const float* __restrict__ attD,
        const int* __restrict__ ei) {
    __shared__ __align__(16) char sbuf[26368];
    int t = threadIdx.x;

    if (blockIdx.x < AE_BLOCKS) {
        // ---- ae body: g_ae{1,2}[e][0:4] = mean(edge_attr[e]) @ P halves ----
        float* sEas = (float*)sbuf;            // 64 x 68 floats (17408B)
        float* sPt = (float*)(sbuf + 17408);   // 8 x 68 (transposed P, 2176B)
        const float4* __restrict__ ea4 = (const float4*)edge_attr;
        long long e0 = (long long)blockIdx.x * 64;

#pragma unroll
        for (int i = 0; i < 2; i++) {
            int idx = t + i * 256;
            sPt[(idx & 7) * 68 + (idx >> 3)] = g_P[idx];
        }
#pragma unroll
        for (int i = 0; i < 4; i++) {
            int idx = t + i * 256;           // 0..1023
            int e = idx >> 4, j4 = idx & 15;
            long long base = (e0 + e) * 48;
            float4 a = ea4[base + j4];
            float4 b = ea4[base + 16 + j4];
            float4 c = ea4[base + 32 + j4];
            float4 m = make_float4((a.x + b.x + c.x) * (1.f / 3.f),
                                   (a.y + b.y + c.y) * (1.f / 3.f),
                                   (a.z + b.z + c.z) * (1.f / 3.f),
                                   (a.w + b.w + c.w) * (1.f / 3.f));
            *(float4*)&sEas[e * 68 + j4 * 4] = m;
        }
        __syncthreads();

        // thread -> (edge pair g = t>>3, head h = t&7); pr reused for 2 edges
        int g = t >> 3, h = t & 7;
        const float* erA = &sEas[(g * 2 + 0) * 68];
        const float* erB = &sEas[(g * 2 + 1) * 68];
        const float* pr = &sPt[h * 68];
        float accA = 0.f, accB = 0.f;
#pragma unroll
        for (int j4 = 0; j4 < 16; j4++) {
            float4 p = *(const float4*)&pr[j4 * 4];
            float4 uA = *(const float4*)&erA[j4 * 4];
            float4 uB = *(const float4*)&erB[j4 * 4];
            accA += uA.x * p.x + uA.y * p.y + uA.z * p.z + uA.w * p.w;
            accB += uB.x * p.x + uB.y * p.y + uB.z * p.z + uB.w * p.w;
        }
        long long eA = e0 + g * 2, eB = eA + 1;
        if (h < 4) {
            g_ae1[eA * 4 + h] = accA;
            g_ae1[eB * 4 + h] = accB;
        } else {
            g_ae2[eA * 4 + (h - 4)] = accA;
            g_ae2[eB * 4 + (h - 4)] = accB;
        }
    } else if (blockIdx.x < AE_BLOCKS + N0_BLOCKS) {
        // ---------------- layer-1 node GEMM (IN=128), K staged in 2 halves --
        const int INp = 132;
        float* Wts = (float*)sbuf;                     // 64 x 68 (one K half)
        float* xs = (float*)(sbuf + 17408);            // 16 x 132
        float* aSs = (float*)(sbuf + 25856);
        float* aDs = (float*)(sbuf + 26112);
        int nb0 = (blockIdx.x - AE_BLOCKS) * 16;

        for (int i = t; i < 16 * 128; i += 256)
            xs[(i >> 7) * INp + (i & 127)] = xin[(size_t)nb0 * 128 + i];
        if (t < 64) { aSs[t] = attS[t]; aDs[t] = attD[t]; }

        int c = t & 63, q = t >> 6;
        u64 p0 = 0ull, p1 = 0ull, p2 = 0ull, p3 = 0ull;
#pragma unroll
        for (int half = 0; half < 2; half++) {
            __syncthreads();
            for (int i = t; i < 4096; i += 256) {
                int cc = i >> 6, kk = i & 63;
                Wts[cc * 68 + kk] = g_W1t[cc * 128 + half * 64 + kk];
            }
            __syncthreads();
            const float* wr = &Wts[c * 68];
            const float* x0 = &xs[(q * 4 + 0) * INp + half * 64];
            const float* x1 = &xs[(q * 4 + 1) * INp + half * 64];
            const float* x2 = &xs[(q * 4 + 2) * INp + half * 64];
            const float* x3 = &xs[(q * 4 + 3) * INp + half * 64];
#pragma unroll
            for (int k = 0; k < 64; k += 4) {
                ulonglong2 w  = *(const ulonglong2*)&wr[k];
                ulonglong2 u0 = *(const ulonglong2*)&x0[k];
                ulonglong2 u1 = *(const ulonglong2*)&x1[k];
                ulonglong2 u2 = *(const ulonglong2*)&x2[k];
                ulonglong2 u3 = *(const ulonglong2*)&x3[k];
                p0 = ffma2(w.x, u0.x, p0); p0 = ffma2(w.y, u0.y, p0);
                p1 = ffma2(w.x, u1.x, p1); p1 = ffma2(w.y, u1.y, p1);
                p2 = ffma2(w.x, u2.x, p2); p2 = ffma2(w.y, u2.y, p2);
                p3 = ffma2(w.x, u3.x, p3); p3 = ffma2(w.y, u3.y, p3);
            }
        }
        float av[4] = {hsum2(p0), hsum2(p1), hsum2(p2), hsum2(p3)};
        float aS = aSs[c], aD = aDs[c];
        int lane = t & 31, head = c >> 4;
        int nb = nb0 + q * 4;
#pragma unroll
        for (int j = 0; j < 4; j++) {
            g_xp[(size_t)(nb + j) * 64 + c] = av[j];
            float r1 = av[j] * aS;
            float r2 = av[j] * aD;
#pragma unroll
            for (int o = 8; o; o >>= 1) {
                r1 += __shfl_xor_sync(0xffffffffu, r1, o);
                r2 += __shfl_xor_sync(0xffffffffu, r2, o);
            }
            if ((lane & 15) == 0) {
                g_asrc[(nb + j) * 4 + head] = r1;
                g_adst[(nb + j) * 4 + head] = r2;
            }
        }
    } else {
        // ---------------- in-degree histogram ------------------------------
        int e = (blockIdx.x - AE_BLOCKS - N0_BLOCKS) * 256 + t;
        bool is64 = ei_is64(ei);
        int d = ei_load(ei, (long long)EE + e, is64);
        atomicAdd(&g_cnt[d], 1);
    }
}

// ---------------------------------------------------------------------------
// FUSED gather + node GEMM (proven). Block = 16 nodes.
// Gather: 16 groups of 16 lanes; lane owns a float4 of channels (head gl>>2).
// GEMM: register-blocked f32x2 on the smem tile.
// ---------------------------------------------------------------------------
template <int LAYER>
__global__ void __launch_bounds__(256) gather_node_kernel(const float* __restrict__ attS,
                                                          const float* __restrict__ attD,
                                                          const float* __restrict__ bias,
                                                          float* __restrict__ outp) {
    const int INp = 68;
    __shared__ float Wts[64 * INp];
    __shared__ float xs[16 * INp];
    __shared__ float aSs[64], aDs[64];
    int t = threadIdx.x;
    const float* __restrict__ Wt = (LAYER == 1) ? g_W2t : g_Wot;
    for (int i = t; i < 64 * 64; i += 256) Wts[(i >> 6) * INp + (i & 63)] = Wt[i];
    if (LAYER == 1 && t < 64) { aSs[t] = attS[t]; aDs[t] = attD[t]; }

    // ---- gather phase ----
    int grp = t >> 4, gl = t & 15;
    int nb0 = blockIdx.x * 16;
    int n = nb0 + grp;
    int h = gl >> 2;
    const float* __restrict__ aSrc = (LAYER == 1) ? g_asrc : g_asrc2;
    const float* __restrict__ aDst = (LAYER == 1) ? g_adst : g_adst2;
    const float* __restrict__ aeL = (LAYER == 1) ? g_ae1 : g_ae2;
    const float4* __restrict__ xp4 =
        (const float4*)((LAYER == 1) ? g_xp : g_xp2);
    float aD = aDst[n * 4 + h];
    int p = g_off[n], pend = g_cur[n];
    float4 acc = make_float4(0.f, 0.f, 0.f, 0.f);
    float den = 0.f;
#pragma unroll 4
    for (; p < pend; p++) {
        int2 se = g_el2[p];
        float a = aSrc[se.x * 4 + h] + aD + aeL[(size_t)se.y * 4 + h];
        a = a > 0.f ? a : 0.2f * a;
        float w = __expf(a);
        float4 v = xp4[se.x * 16 + gl];
        acc.x += w * v.x;
        acc.y += w * v.y;
        acc.z += w * v.z;
        acc.w += w * v.w;
        den += w;
    }
    float inv = 1.f / fmaxf(den, 1e-16f);
    *(float4*)&xs[grp * INp + gl * 4] =
        make_float4(fmaxf(acc.x * inv, 0.f), fmaxf(acc.y * inv, 0.f),
                    fmaxf(acc.z * inv, 0.f), fmaxf(acc.w * inv, 0.f));
    __syncthreads();

    // ---- GEMM phase ----
    int c = t & 63, q = t >> 6;
    const float* wr = &Wts[c * INp];
    const float* x0 = &xs[(q * 4 + 0) * INp];
    const float* x1 = &xs[(q * 4 + 1) * INp];
    const float* x2 = &xs[(q * 4 + 2) * INp];
    const float* x3 = &xs[(q * 4 + 3) * INp];
    u64 p0 = 0ull, p1 = 0ull, p2 = 0ull, p3 = 0ull;
#pragma unroll
    for (int k = 0; k < 64; k += 4) {
        ulonglong2 w  = *(const ulonglong2*)&wr[k];
        ulonglong2 u0 = *(const ulonglong2*)&x0[k];
        ulonglong2 u1 = *(const ulonglong2*)&x1[k];
        ulonglong2 u2 = *(const ulonglong2*)&x2[k];
        ulonglong2 u3 = *(const ulonglong2*)&x3[k];
        p0 = ffma2(w.x, u0.x, p0); p0 = ffma2(w.y, u0.y, p0);
        p1 = ffma2(w.x, u1.x, p1); p1 = ffma2(w.y, u1.y, p1);
        p2 = ffma2(w.x, u2.x, p2); p2 = ffma2(w.y, u2.y, p2);
        p3 = ffma2(w.x, u3.x, p3); p3 = ffma2(w.y, u3.y, p3);
    }
    float a0 = hsum2(p0), a1 = hsum2(p1), a2 = hsum2(p2), a3 = hsum2(p3);
    int nb = nb0 + q * 4;
    if (LAYER == 2) {
        float b = bias[c];
        outp[(size_t)(nb + 0) * 64 + c] = a0 + b;
        outp[(size_t)(nb + 1) * 64 + c] = a1 + b;
        outp[(size_t)(nb + 2) * 64 + c] = a2 + b;
        outp[(size_t)(nb + 3) * 64 + c] = a3 + b;
    } else {
        float aS = aSs[c], aDv = aDs[c];
        int lane = t & 31, head = c >> 4;
        float av[4] = {a0, a1, a2, a3};
#pragma unroll
        for (int j = 0; j < 4; j++) {
            g_xp2[(size_t)(nb + j) * 64 + c] = av[j];
            float r1 = av[j] * aS;
            float r2 = av[j] * aDv;
#pragma unroll
            for (int o = 8; o; o >>= 1) {
                r1 += __shfl_xor_sync(0xffffffffu, r1, o);
                r2 += __shfl_xor_sync(0xffffffffu, r2, o);
            }
            if ((lane & 15) == 0) {
                g_asrc2[(nb + j) * 4 + head] = r1;
                g_adst2[(nb + j) * 4 + head] = r2;
            }
        }
    }
}

// ---------------------------------------------------------------------------
extern "C" void kernel_launch(void* const* d_in, const int* in_sizes, int n_in,
                              void* d_out, int out_size) {
    const float* x = (const float*)d_in[0];
    const int* ei = (const int*)d_in[1];
    const float* edge_attr = (const float*)d_in[2];
    const float* W1 = (const float*)d_in[3];
    const float* We1 = (const float*)d_in[4];
    const float* as1 = (const float*)d_in[5];
    const float* ad1 = (const float*)d_in[6];
    const float* ae1 = (const float*)d_in[7];
    const float* W2 = (const float*)d_in[8];
    const float* We2 = (const float*)d_in[9];
    const float* as2 = (const float*)d_in[10];
    const float* ad2 = (const float*)d_in[11];
    const float* ae2 = (const float*)d_in[12];
    const float* Wout = (const float*)d_in[13];
    const float* bout = (const float*)d_in[14];
    float* out = (float*)d_out;

    // 1: zero cnt/total + P fold + weight transpose
    setup_kernel<<<NBLK1 + 1 + 32, 256>>>(We1, We2, ae1, ae2, W1, W2, Wout);
    // 2: big fused kernel (ae stream + layer-1 node GEMM + degree histogram)
    fused_ae_node0_kernel<<<AE_BLOCKS + N0_BLOCKS + HIST_BLOCKS, 256>>>(
        edge_attr, x, as1, ad1, ei);
    // 3-4: CSR segments (bump alloc) + fill
    alloc_kernel<<<NBLK1, 256>>>();
    fill_kernel<<<EE / 256, 256>>>(ei);
    // 5: gather layer 1 + layer-2 node GEMM (writes xp2/att2)
    gather_node_kernel<1><<<NN / 16, 256>>>(as2, ad2, nullptr, nullptr);
    // 6: gather layer 2 + output GEMM
    gather_node_kernel<2><<<NN / 16, 256>>>(nullptr, nullptr, bout, out);
}

// round 16
// speedup vs baseline: 1.0480x; 1.0027x over previous
#include <cuda_runtime.h>

#define NN 100000
#define EE 1600000
#define NBLK1 391             // ceil(NN/256)
#define AE_BLOCKS (EE / 64)   // 25000 (64 edges per ae block)
#define N0_BLOCKS (NN / 16)   // 6250
#define HIST_BLOCKS (EE / 256) // 6250

typedef unsigned long long u64;

// ---------------- scratch (device globals; no allocation allowed) ----------
__device__ __align__(16) float g_ae1[EE * 4];    // EDGE-ordered layer-1 logits (25.6MB)
__device__ __align__(16) float g_ae2[EE * 4];    // EDGE-ordered layer-2 logits (25.6MB)
__device__ __align__(16) float g_xp[NN * 64];    // layer-1 projected feats
__device__ __align__(16) float g_xp2[NN * 64];   // layer-2 projected feats
__device__ __align__(16) int2  g_el2[EE];        // CSR: (src, edge_id) per slot
__device__ float g_asrc[NN * 4],  g_adst[NN * 4];    // layer-1 att dots
__device__ float g_asrc2[NN * 4], g_adst2[NN * 4];   // layer-2 att dots
__device__ int   g_cnt[NN];
__device__ int   g_off[NN];
__device__ int   g_cur[NN];      // fill cursor; after fill = segment end
__device__ int   g_total;        // bump allocator
__device__ float g_P[512];       // folded [64 j][8 h]
__device__ float g_W1t[64 * 128];   // transposed weights [c][k]
__device__ float g_W2t[64 * 64];
__device__ float g_Wot[64 * 64];

// ---------------------------------------------------------------------------
__device__ __forceinline__ u64 ffma2(u64 a, u64 b, u64 c) {
    u64 d;
    asm("fma.rn.f32x2 %0, %1, %2, %3;" : "=l"(d) : "l"(a), "l"(b), "l"(c));
    return d;
}
__device__ __forceinline__ float hsum2(u64 p) {
    return __uint_as_float((unsigned)p) + __uint_as_float((unsigned)(p >> 32));
}

// edge_index dtype hedge (int64 vs int32): int64 little-endian has zero odd words.
__device__ __forceinline__ bool ei_is64(const int* __restrict__ ei) {
    return (ei[1] | ei[3] | ei[5] | ei[7]) == 0;
}
__device__ __forceinline__ int ei_load(const int* __restrict__ ei, long long pos, bool is64) {
    return is64 ? ei[pos * 2] : ei[pos];
}

// ---------------------------------------------------------------------------
// setup pieces (3 separate launches so the big fused kernel lands at the
// ncu-profiled slot #4; identical total work to the old single setup kernel)
// ---------------------------------------------------------------------------
__global__ void zero_cnt_kernel() {
    int i = blockIdx.x * 256 + threadIdx.x;
    if (i < NN) g_cnt[i] = 0;
    if (i == 0) g_total = 0;
}
__global__ void pfold_kernel(const float* __restrict__ We1,
                             const float* __restrict__ We2,
                             const float* __restrict__ ate1,
                             const float* __restrict__ ate2) {
    __shared__ float A2p[64 * 4];
    int j = threadIdx.x;   // 0..63
#pragma unroll
    for (int h = 0; h < 4; h++) {
        float s = 0.f;
#pragma unroll
        for (int c = 0; c < 16; c++) s += We2[j * 64 + h * 16 + c] * ate2[h * 16 + c];
        A2p[j * 4 + h] = s;
    }
    __syncthreads();
#pragma unroll
    for (int h = 0; h < 4; h++) {
        float s = 0.f;
#pragma unroll
        for (int c = 0; c < 16; c++) s += We1[j * 64 + h * 16 + c] * ate1[h * 16 + c];
        g_P[j * 8 + h] = s;
    }
#pragma unroll
    for (int h = 0; h < 4; h++) {
        float s = 0.f;
        for (int k = 0; k < 64; k++) s += We1[j * 64 + k] * A2p[k * 4 + h];
        g_P[j * 8 + 4 + h] = s;
    }
}
__global__ void transpose_kernel(const float* __restrict__ W1,
                                 const float* __restrict__ W2,
                                 const float* __restrict__ Wo) {
    int i = blockIdx.x * 256 + threadIdx.x;   // 0..8191
    int k = i >> 6, c = i & 63;
    g_W1t[c * 128 + k] = W1[i];
    if (i < 4096) {
        g_W2t[c * 64 + k] = W2[i];
        g_Wot[c * 64 + k] = Wo[i];
    }
}

// ---------------------------------------------------------------------------
// CSR build helpers: warp-aggregated bump alloc, fill
// (histogram lives inside the fused kernel; alloc order arbitrary-but-
//  consistent; per-node sums unaffected)
// ---------------------------------------------------------------------------
__global__ void __launch_bounds__(256) alloc_kernel() {
    int i = blockIdx.x * 256 + threadIdx.x;
    int lane = threadIdx.x & 31;
    int c = (i < NN) ? g_cnt[i] : 0;
    int incl = c;
#pragma unroll
    for (int o = 1; o < 32; o <<= 1) {
        int v = __shfl_up_sync(0xffffffffu, incl, o);
        if (lane >= o) incl += v;
    }
    int wsum = __shfl_sync(0xffffffffu, incl, 31);
    int base = 0;
    if (lane == 31) base = atomicAdd(&g_total, wsum);
    base = __shfl_sync(0xffffffffu, base, 31);
    if (i < NN) {
        int off = base + incl - c;
        g_off[i] = off;
        g_cur[i] = off;
    }
}
__global__ void fill_kernel(const int* __restrict__ ei) {
    int e = blockIdx.x * 256 + threadIdx.x;
    bool is64 = ei_is64(ei);
    int s = ei_load(ei, e, is64);
    int d = ei_load(ei, (long long)EE + e, is64);
    int pos = atomicAdd(&g_cur[d], 1);
    g_el2[pos] = make_int2(s, e);
}

// ---------------------------------------------------------------------------
// FUSED kernel, 3 sequential block ranges:
//  [0, AE_BLOCKS)            : ae body (64 edges/block, 2-edge P-register
//                              reuse; coalesced edge-ordered writes)
//  [AE, AE+N0)               : layer-1 node GEMM (IN=128, f32x2, proven)
//  [AE+N0, AE+N0+HIST)       : in-degree histogram (independent; absorbed by
//                              the DRAM-bound phase)
// __launch_bounds__(256, 6): cap regs at 42 -> 6 blocks/SM (was 5 @47 regs)
// to raise resident warps feeding the DRAM stream during the ae phase.
// ---------------------------------------------------------------------------
__global__ void __launch_bounds__(256, 6) fused_ae_node0_kernel(
        const float* __restrict__ edge_attr,
        const float* __restrict__ xin,
        const float* __restrict__ attS,
        const float* __restrict__ attD,
        const int* __restrict__ ei) {
    __shared__ __align__(16) char sbuf[26368];
    int t = threadIdx.x;

    if (blockIdx.x < AE_BLOCKS) {
        // ---- ae body: g_ae{1,2}[e][0:4] = mean(edge_attr[e]) @ P halves ----
        float* sEas = (float*)sbuf;            // 64 x 68 floats (17408B)
        float* sPt = (float*)(sbuf + 17408);   // 8 x 68 (transposed P, 2176B)
        const float4* __restrict__ ea4 = (const float4*)edge_attr;
        long long e0 = (long long)blockIdx.x * 64;

#pragma unroll
        for (int i = 0; i < 2; i++) {
            int idx = t + i * 256;
            sPt[(idx & 7) * 68 + (idx >> 3)] = g_P[idx];
        }
#pragma unroll
        for (int i = 0; i < 4; i++) {
            int idx = t + i * 256;           // 0..1023
            int e = idx >> 4, j4 = idx & 15;
            long long base = (e0 + e) * 48;
            float4 a = ea4[base + j4];
            float4 b = ea4[base + 16 + j4];
            float4 c = ea4[base + 32 + j4];
            float4 m = make_float4((a.x + b.x + c.x) * (1.f / 3.f),
                                   (a.y + b.y + c.y) * (1.f / 3.f),
                                   (a.z + b.z + c.z) * (1.f / 3.f),
                                   (a.w + b.w + c.w) * (1.f / 3.f));
            *(float4*)&sEas[e * 68 + j4 * 4] = m;
        }
        __syncthreads();

        // thread -> (edge pair g = t>>3, head h = t&7); pr reused for 2 edges
        int g = t >> 3, h = t & 7;
        const float* erA = &sEas[(g * 2 + 0) * 68];
        const float* erB = &sEas[(g * 2 + 1) * 68];
        const float* pr = &sPt[h * 68];
        float accA = 0.f, accB = 0.f;
#pragma unroll
        for (int j4 = 0; j4 < 16; j4++) {
            float4 p = *(const float4*)&pr[j4 * 4];
            float4 uA = *(const float4*)&erA[j4 * 4];
            float4 uB = *(const float4*)&erB[j4 * 4];
            accA += uA.x * p.x + uA.y * p.y + uA.z * p.z + uA.w * p.w;
            accB += uB.x * p.x + uB.y * p.y + uB.z * p.z + uB.w * p.w;
        }
        long long eA = e0 + g * 2, eB = eA + 1;
        if (h < 4) {
            g_ae1[eA * 4 + h] = accA;
            g_ae1[eB * 4 + h] = accB;
        } else {
            g_ae2[eA * 4 + (h - 4)] = accA;
            g_ae2[eB * 4 + (h - 4)] = accB;
        }
    } else if (blockIdx.x < AE_BLOCKS + N0_BLOCKS) {
        // ---------------- layer-1 node GEMM (IN=128), K staged in 2 halves --
        const int INp = 132;
        float* Wts = (float*)sbuf;                     // 64 x 68 (one K half)
        float* xs = (float*)(sbuf + 17408);            // 16 x 132
        float* aSs = (float*)(sbuf + 25856);
        float* aDs = (float*)(sbuf + 26112);
        int nb0 = (blockIdx.x - AE_BLOCKS) * 16;

        for (int i = t; i < 16 * 128; i += 256)
            xs[(i >> 7) * INp + (i & 127)] = xin[(size_t)nb0 * 128 + i];
        if (t < 64) { aSs[t] = attS[t]; aDs[t] = attD[t]; }

        int c = t & 63, q = t >> 6;
        u64 p0 = 0ull, p1 = 0ull, p2 = 0ull, p3 = 0ull;
#pragma unroll
        for (int half = 0; half < 2; half++) {
            __syncthreads();
            for (int i = t; i < 4096; i += 256) {
                int cc = i >> 6, kk = i & 63;
                Wts[cc * 68 + kk] = g_W1t[cc * 128 + half * 64 + kk];
            }
            __syncthreads();
            const float* wr = &Wts[c * 68];
            const float* x0 = &xs[(q * 4 + 0) * INp + half * 64];
            const float* x1 = &xs[(q * 4 + 1) * INp + half * 64];
            const float* x2 = &xs[(q * 4 + 2) * INp + half * 64];
            const float* x3 = &xs[(q * 4 + 3) * INp + half * 64];
#pragma unroll
            for (int k = 0; k < 64; k += 4) {
                ulonglong2 w  = *(const ulonglong2*)&wr[k];
                ulonglong2 u0 = *(const ulonglong2*)&x0[k];
                ulonglong2 u1 = *(const ulonglong2*)&x1[k];
                ulonglong2 u2 = *(const ulonglong2*)&x2[k];
                ulonglong2 u3 = *(const ulonglong2*)&x3[k];
                p0 = ffma2(w.x, u0.x, p0); p0 = ffma2(w.y, u0.y, p0);
                p1 = ffma2(w.x, u1.x, p1); p1 = ffma2(w.y, u1.y, p1);
                p2 = ffma2(w.x, u2.x, p2); p2 = ffma2(w.y, u2.y, p2);
                p3 = ffma2(w.x, u3.x, p3); p3 = ffma2(w.y, u3.y, p3);
            }
        }
        float av[4] = {hsum2(p0), hsum2(p1), hsum2(p2), hsum2(p3)};
        float aS = aSs[c], aD = aDs[c];
        int lane = t & 31, head = c >> 4;
        int nb = nb0 + q * 4;
#pragma unroll
        for (int j = 0; j < 4; j++) {
            g_xp[(size_t)(nb + j) * 64 + c] = av[j];
            float r1 = av[j] * aS;
            float r2 = av[j] * aD;
#pragma unroll
            for (int o = 8; o; o >>= 1) {
                r1 += __shfl_xor_sync(0xffffffffu, r1, o);
                r2 += __shfl_xor_sync(0xffffffffu, r2, o);
            }
            if ((lane & 15) == 0) {
                g_asrc[(nb + j) * 4 + head] = r1;
                g_adst[(nb + j) * 4 + head] = r2;
            }
        }
    } else {
        // ---------------- in-degree histogram ------------------------------
        int e = (blockIdx.x - AE_BLOCKS - N0_BLOCKS) * 256 + t;
        bool is64 = ei_is64(ei);
        int d = ei_load(ei, (long long)EE + e, is64);
        atomicAdd(&g_cnt[d], 1);
    }
}

// ---------------------------------------------------------------------------
// FUSED gather + node GEMM (proven). Block = 16 nodes.
// Gather: 16 groups of 16 lanes; lane owns a float4 of channels (head gl>>2).
// GEMM: register-blocked f32x2 on the smem tile.
// ---------------------------------------------------------------------------
template <int LAYER>
__global__ void __launch_bounds__(256) gather_node_kernel(const float* __restrict__ attS,
                                                          const float* __restrict__ attD,
                                                          const float* __restrict__ bias,
                                                          float* __restrict__ outp) {
    const int INp = 68;
    __shared__ float Wts[64 * INp];
    __shared__ float xs[16 * INp];
    __shared__ float aSs[64], aDs[64];
    int t = threadIdx.x;
    const float* __restrict__ Wt = (LAYER == 1) ? g_W2t : g_Wot;
    for (int i = t; i < 64 * 64; i += 256) Wts[(i >> 6) * INp + (i & 63)] = Wt[i];
    if (LAYER == 1 && t < 64) { aSs[t] = attS[t]; aDs[t] = attD[t]; }

    // ---- gather phase ----
    int grp = t >> 4, gl = t & 15;
    int nb0 = blockIdx.x * 16;
    int n = nb0 + grp;
    int h = gl >> 2;
    const float* __restrict__ aSrc = (LAYER == 1) ? g_asrc : g_asrc2;
    const float* __restrict__ aDst = (LAYER == 1) ? g_adst : g_adst2;
    const float* __restrict__ aeL = (LAYER == 1) ? g_ae1 : g_ae2;
    const float4* __restrict__ xp4 =
        (const float4*)((LAYER == 1) ? g_xp : g_xp2);
    float aD = aDst[n * 4 + h];
    int p = g_off[n], pend = g_cur[n];
    float4 acc = make_float4(0.f, 0.f, 0.f, 0.f);
    float den = 0.f;
#pragma unroll 4
    for (; p < pend; p++) {
        int2 se = g_el2[p];
        float a = aSrc[se.x * 4 + h] + aD + aeL[(size_t)se.y * 4 + h];
        a = a > 0.f ? a : 0.2f * a;
        float w = __expf(a);
        float4 v = xp4[se.x * 16 + gl];
        acc.x += w * v.x;
        acc.y += w * v.y;
        acc.z += w * v.z;
        acc.w += w * v.w;
        den += w;
    }
    float inv = 1.f / fmaxf(den, 1e-16f);
    *(float4*)&xs[grp * INp + gl * 4] =
        make_float4(fmaxf(acc.x * inv, 0.f), fmaxf(acc.y * inv, 0.f),
                    fmaxf(acc.z * inv, 0.f), fmaxf(acc.w * inv, 0.f));
    __syncthreads();

    // ---- GEMM phase ----
    int c = t & 63, q = t >> 6;
    const float* wr = &Wts[c * INp];
    const float* x0 = &xs[(q * 4 + 0) * INp];
    const float* x1 = &xs[(q * 4 + 1) * INp];
    const float* x2 = &xs[(q * 4 + 2) * INp];
    const float* x3 = &xs[(q * 4 + 3) * INp];
    u64 p0 = 0ull, p1 = 0ull, p2 = 0ull, p3 = 0ull;
#pragma unroll
    for (int k = 0; k < 64; k += 4) {
        ulonglong2 w  = *(const ulonglong2*)&wr[k];
        ulonglong2 u0 = *(const ulonglong2*)&x0[k];
        ulonglong2 u1 = *(const ulonglong2*)&x1[k];
        ulonglong2 u2 = *(const ulonglong2*)&x2[k];
        ulonglong2 u3 = *(const ulonglong2*)&x3[k];
        p0 = ffma2(w.x, u0.x, p0); p0 = ffma2(w.y, u0.y, p0);
        p1 = ffma2(w.x, u1.x, p1); p1 = ffma2(w.y, u1.y, p1);
        p2 = ffma2(w.x, u2.x, p2); p2 = ffma2(w.y, u2.y, p2);
        p3 = ffma2(w.x, u3.x, p3); p3 = ffma2(w.y, u3.y, p3);
    }
    float a0 = hsum2(p0), a1 = hsum2(p1), a2 = hsum2(p2), a3 = hsum2(p3);
    int nb = nb0 + q * 4;
    if (LAYER == 2) {
        float b = bias[c];
        outp[(size_t)(nb + 0) * 64 + c] = a0 + b;
        outp[(size_t)(nb + 1) * 64 + c] = a1 + b;
        outp[(size_t)(nb + 2) * 64 + c] = a2 + b;
        outp[(size_t)(nb + 3) * 64 + c] = a3 + b;
    } else {
        float aS = aSs[c], aDv = aDs[c];
        int lane = t & 31, head = c >> 4;
        float av[4] = {a0, a1, a2, a3};
#pragma unroll
        for (int j = 0; j < 4; j++) {
            g_xp2[(size_t)(nb + j) * 64 + c] = av[j];
            float r1 = av[j] * aS;
            float r2 = av[j] * aDv;
#pragma unroll
            for (int o = 8; o; o >>= 1) {
                r1 += __shfl_xor_sync(0xffffffffu, r1, o);
                r2 += __shfl_xor_sync(0xffffffffu, r2, o);
            }
            if ((lane & 15) == 0) {
                g_asrc2[(nb + j) * 4 + head] = r1;
                g_adst2[(nb + j) * 4 + head] = r2;
            }
        }
    }
}

// ---------------------------------------------------------------------------
extern "C" void kernel_launch(void* const* d_in, const int* in_sizes, int n_in,
                              void* d_out, int out_size) {
    const float* x = (const float*)d_in[0];
    const int* ei = (const int*)d_in[1];
    const float* edge_attr = (const float*)d_in[2];
    const float* W1 = (const float*)d_in[3];
    const float* We1 = (const float*)d_in[4];
    const float* as1 = (const float*)d_in[5];
    const float* ad1 = (const float*)d_in[6];
    const float* ae1 = (const float*)d_in[7];
    const float* W2 = (const float*)d_in[8];
    const float* We2 = (const float*)d_in[9];
    const float* as2 = (const float*)d_in[10];
    const float* ad2 = (const float*)d_in[11];
    const float* ae2 = (const float*)d_in[12];
    const float* Wout = (const float*)d_in[13];
    const float* bout = (const float*)d_in[14];
    float* out = (float*)d_out;

    // 1-3: setup split into 3 launches (same work; lands fused at profiled #4)
    zero_cnt_kernel<<<NBLK1, 256>>>();
    pfold_kernel<<<1, 64>>>(We1, We2, ae1, ae2);
    transpose_kernel<<<32, 256>>>(W1, W2, Wout);
    // 4: big fused kernel (ae stream + layer-1 node GEMM + degree histogram)
    fused_ae_node0_kernel<<<AE_BLOCKS + N0_BLOCKS + HIST_BLOCKS, 256>>>(
        edge_attr, x, as1, ad1, ei);
    // 5-6: CSR segments (bump alloc) + fill
    alloc_kernel<<<NBLK1, 256>>>();
    fill_kernel<<<EE / 256, 256>>>(ei);
    // 7: gather layer 1 + layer-2 node GEMM (writes xp2/att2)
    gather_node_kernel<1><<<NN / 16, 256>>>(as2, ad2, nullptr, nullptr);
    // 8: gather layer 2 + output GEMM
    gather_node_kernel<2><<<NN / 16, 256>>>(nullptr, nullptr, bout, out);
}